// round 1
// baseline (speedup 1.0000x reference)
#include <cuda_runtime.h>
#include <stdint.h>

// Problem: ragged node-batch -> batch reconstruction.
// Inputs (metadata order):
//   d_in[0]: src         [L, NB]      float32 (trailing dim 1 squeezed)
//   d_in[1]: memory_bank [L, NB, D]   float32
//   d_in[2]: lengths     [NB]         int32
//   d_in[3]: recover     [NB]         int32
//   (d_in[4], d_in[5]: scalar ints, unused — all shapes derived from sizes)
// Output d_out (flat, tuple order):
//   src_out     [MAX_LEN, B]      (MAX_LEN = N*L)
//   mb_out      [MAX_LEN, B, D]
//   hidden      [B, D]
//   lengths_out [B]

// ---------------------------------------------------------------------------
// Kernel 1: initialize padded regions.
// For each batch row b, token slots [len_b, MAX_LEN) are padding:
//   mb_out rows -> 0.0, src_out -> 1.0. Also zeroes hidden accumulators.
// Valid slots [0, len_b) are fully covered by the scatter kernel (offsets are
// exclusive prefix sums -> contiguous coverage), so we skip them here.
// ---------------------------------------------------------------------------
__global__ void init_pad_kernel(const int* __restrict__ lengths,
                                float* __restrict__ src_out,
                                float* __restrict__ mb_out,
                                float* __restrict__ hidden,
                                int B, int N, int D, int MAX_LEN)
{
    const int b = blockIdx.x;
    const int y = blockIdx.y;
    const int ny = gridDim.y;

    __shared__ int s_lenb;
    if (threadIdx.x == 0) {
        int s = 0;
        const int* lp = lengths + b * N;
        #pragma unroll 4
        for (int i = 0; i < N; ++i) s += lp[i];
        s_lenb = s;
    }
    __syncthreads();
    const int len_b = s_lenb;

    // zero hidden accumulators (done by y==0 planes)
    if (y == 0) {
        for (int d = threadIdx.x; d < D; d += blockDim.x)
            hidden[(size_t)b * D + d] = 0.0f;
    }

    // mb_out tail rows -> 0 (vectorized: 4 rows per block iteration)
    const int lanes = D >> 2;                   // float4 lanes per row (64)
    const int rowsPerIter = blockDim.x / lanes; // 4
    const int lane = threadIdx.x % lanes;
    const int rsub = threadIdx.x / lanes;
    const float4 z4 = make_float4(0.f, 0.f, 0.f, 0.f);
    for (int t = len_b + y * rowsPerIter + rsub; t < MAX_LEN; t += ny * rowsPerIter) {
        float4* row = reinterpret_cast<float4*>(mb_out + ((size_t)t * B + b) * D);
        row[lane] = z4;
    }

    // src_out tail -> 1.0
    for (int t = len_b + y * blockDim.x + threadIdx.x; t < MAX_LEN; t += ny * blockDim.x)
        src_out[(size_t)t * B + b] = 1.0f;
}

// ---------------------------------------------------------------------------
// Kernel 2: scatter valid token rows + fused mean-pool reduction.
// One block per node (b, n). blockDim.x == D (256): thread d handles feature d.
// ---------------------------------------------------------------------------
__global__ void scatter_kernel(const float* __restrict__ src,
                               const float* __restrict__ mb,
                               const int* __restrict__ lengths,
                               const int* __restrict__ recover,
                               float* __restrict__ src_out,
                               float* __restrict__ mb_out,
                               float* __restrict__ hidden,
                               float* __restrict__ lengths_out,
                               int B, int N, int D, int NB)
{
    const int nb = blockIdx.x;
    const int b = nb / N;
    const int n = nb - b * N;

    extern __shared__ int s_len[]; // N ints
    for (int i = threadIdx.x; i < N; i += blockDim.x)
        s_len[i] = lengths[b * N + i];
    __syncthreads();

    int off = 0, len_b = 0;
    #pragma unroll 4
    for (int i = 0; i < N; ++i) {
        int li = s_len[i];
        len_b += li;
        if (i < n) off += li;
    }
    const int len = s_len[n];

    const int d = threadIdx.x;
    const float* __restrict__ in_base  = mb + (size_t)nb * D + d;
    float* __restrict__ out_base = mb_out + ((size_t)off * B + b) * D + d;
    const size_t in_stride  = (size_t)NB * D;
    const size_t out_stride = (size_t)B * D;

    float acc = 0.0f;
    int p = 0;
    // unroll x4 for MLP
    for (; p + 3 < len; p += 4) {
        float v0 = in_base[(size_t)(p + 0) * in_stride];
        float v1 = in_base[(size_t)(p + 1) * in_stride];
        float v2 = in_base[(size_t)(p + 2) * in_stride];
        float v3 = in_base[(size_t)(p + 3) * in_stride];
        out_base[(size_t)(p + 0) * out_stride] = v0;
        out_base[(size_t)(p + 1) * out_stride] = v1;
        out_base[(size_t)(p + 2) * out_stride] = v2;
        out_base[(size_t)(p + 3) * out_stride] = v3;
        acc += v0 + v1 + v2 + v3;
    }
    for (; p < len; ++p) {
        float v = in_base[(size_t)p * in_stride];
        out_base[(size_t)p * out_stride] = v;
        acc += v;
    }

    if (len_b > 0)
        atomicAdd(&hidden[(size_t)b * D + d], acc / (float)len_b);

    // src scatter: src_g[b,n,p] = src[p, recover[nb]]
    const int rc = recover[nb];
    for (int q = threadIdx.x; q < len; q += blockDim.x)
        src_out[(size_t)(off + q) * B + b] = src[(size_t)q * NB + rc];

    if (n == 0 && threadIdx.x == 0)
        lengths_out[b] = (float)len_b;
}

extern "C" void kernel_launch(void* const* d_in, const int* in_sizes, int n_in,
                              void* d_out, int out_size)
{
    const float* src     = (const float*)d_in[0];
    const float* mb      = (const float*)d_in[1];
    const int*   lengths = (const int*)d_in[2];
    const int*   recover = (const int*)d_in[3];

    // Derive shapes from sizes (no device reads; graph-capturable).
    const long long NB = in_sizes[2];
    const long long L  = in_sizes[0] / NB;          // src = L*NB
    const long long D  = in_sizes[1] / in_sizes[0]; // mb  = L*NB*D
    // out_size = B*(D+1)*(N*L+1) = (D+1)*(NB*L + B)
    const long long B  = (long long)out_size / (D + 1) - NB * L;
    const long long N  = NB / B;
    const long long MAX_LEN = N * L;

    float* out = (float*)d_out;
    float* src_out     = out;
    float* mb_out      = out + (size_t)MAX_LEN * B;
    float* hidden      = mb_out + (size_t)MAX_LEN * B * D;
    float* lengths_out = hidden + (size_t)B * D;

    // Kernel 1: pad init
    {
        dim3 grid((unsigned)B, 64);
        init_pad_kernel<<<grid, 256>>>(lengths, src_out, mb_out, hidden,
                                       (int)B, (int)N, (int)D, (int)MAX_LEN);
    }
    // Kernel 2: scatter + fused reduction
    {
        dim3 grid((unsigned)NB);
        size_t shm = (size_t)N * sizeof(int);
        scatter_kernel<<<grid, (unsigned)D, shm>>>(src, mb, lengths, recover,
                                                   src_out, mb_out, hidden, lengths_out,
                                                   (int)B, (int)N, (int)D, (int)NB);
    }
}

// round 2
// speedup vs baseline: 1.1396x; 1.1396x over previous
#include <cuda_runtime.h>
#include <stdint.h>

// Ragged node-batch -> batch reconstruction.
// Inputs: src [L,NB], memory_bank [L,NB,D], lengths [NB], recover [NB]
// Output (flat): src_out [MAX_LEN,B], mb_out [MAX_LEN,B,D], hidden [B,D], lengths_out [B]
// B=32, N=64, L=128, D=256, NB=2048, MAX_LEN=8192 (all derived from sizes).

// ---------------------------------------------------------------------------
// Kernel 0 (tiny): zero the hidden accumulator (d_out is poisoned).
// ---------------------------------------------------------------------------
__global__ void zero_hidden_kernel(float* __restrict__ hidden, int n4)
{
    int i = blockIdx.x * blockDim.x + threadIdx.x;
    if (i < n4)
        reinterpret_cast<float4*>(hidden)[i] = make_float4(0.f, 0.f, 0.f, 0.f);
}

// ---------------------------------------------------------------------------
// Kernel 1 (fused): per-node scatter (float4-vectorized) + fused mean-pool
// partial reduction + tail zero/one fill. One block per node (b, n),
// 256 threads. Lane = float4 column (64 lanes/row), rsub = row subgroup (4).
// ---------------------------------------------------------------------------
__global__ void __launch_bounds__(256)
fused_scatter_kernel(const float* __restrict__ src,
                     const float* __restrict__ mb,
                     const int* __restrict__ lengths,
                     const int* __restrict__ recover,
                     float* __restrict__ src_out,
                     float* __restrict__ mb_out,
                     float* __restrict__ hidden,
                     float* __restrict__ lengths_out,
                     int B, int N, int D, int NB, int MAX_LEN)
{
    const int nb = blockIdx.x;
    const int b = nb / N;
    const int n = nb - b * N;
    const int tid  = threadIdx.x;
    const int lanes = D >> 2;              // float4 lanes per row (64)
    const int lane = tid & (lanes - 1);
    const int rsub = tid >> 6;             // 0..3 (blockDim/lanes == 4)

    __shared__ int s_len[64];
    __shared__ float4 s_acc[4][64];

    for (int i = tid; i < N; i += blockDim.x)
        s_len[i] = lengths[b * N + i];
    __syncthreads();

    int off = 0, len_b = 0;
    #pragma unroll 8
    for (int i = 0; i < N; ++i) {
        int li = s_len[i];
        len_b += li;
        if (i < n) off += li;
    }
    const int len = s_len[n];

    // -------- scatter valid rows (float4), 4 rows in flight per iteration ----
    const float4* __restrict__ in4  =
        reinterpret_cast<const float4*>(mb) + (size_t)nb * lanes + lane;
    float4* __restrict__ out4 =
        reinterpret_cast<float4*>(mb_out) + ((size_t)off * B + b) * lanes + lane;
    const size_t in_stride  = (size_t)NB * lanes;   // float4 stride per token row
    const size_t out_stride = (size_t)B * lanes;

    float4 acc = make_float4(0.f, 0.f, 0.f, 0.f);
    for (int p = rsub; p < len; p += 4) {
        float4 v = in4[(size_t)p * in_stride];
        out4[(size_t)p * out_stride] = v;
        acc.x += v.x; acc.y += v.y; acc.z += v.z; acc.w += v.w;
    }
    s_acc[rsub][lane] = acc;

    // -------- src scatter: src_g[b,n,p] = src[p, recover[nb]] ---------------
    const int rc = recover[nb];
    for (int q = tid; q < len; q += blockDim.x)
        src_out[(size_t)(off + q) * B + b] = src[(size_t)q * NB + rc];

    __syncthreads();

    // -------- hidden partial: reduce 4 subgroups, then 4 atomics/thread -----
    if (rsub == 0 && len_b > 0) {
        float4 a0 = s_acc[0][lane], a1 = s_acc[1][lane];
        float4 a2 = s_acc[2][lane], a3 = s_acc[3][lane];
        float inv = 1.0f / (float)len_b;
        float* h = hidden + (size_t)b * D + lane * 4;
        atomicAdd(h + 0, (a0.x + a1.x + a2.x + a3.x) * inv);
        atomicAdd(h + 1, (a0.y + a1.y + a2.y + a3.y) * inv);
        atomicAdd(h + 2, (a0.z + a1.z + a2.z + a3.z) * inv);
        atomicAdd(h + 3, (a0.w + a1.w + a2.w + a3.w) * inv);
    }

    // -------- tail fill: rows [len_b, MAX_LEN) of batch b, split across N ---
    // mb_out tail rows -> 0 (contiguous 1KB rows, float4).
    {
        const float4 z4 = make_float4(0.f, 0.f, 0.f, 0.f);
        // block handles rows r = len_b + (k*4 + rsub)*N + n
        for (int r = len_b + rsub * N + n; r < MAX_LEN; r += 4 * N) {
            float4* row = reinterpret_cast<float4*>(mb_out) + ((size_t)r * B + b) * lanes;
            row[lane] = z4;
        }
    }
    // src_out tail -> 1.0
    {
        const int T = MAX_LEN - len_b;
        for (int i = n * blockDim.x + tid; i < T; i += N * blockDim.x)
            src_out[(size_t)(len_b + i) * B + b] = 1.0f;
    }

    if (n == 0 && tid == 0)
        lengths_out[b] = (float)len_b;
}

extern "C" void kernel_launch(void* const* d_in, const int* in_sizes, int n_in,
                              void* d_out, int out_size)
{
    const float* src     = (const float*)d_in[0];
    const float* mb      = (const float*)d_in[1];
    const int*   lengths = (const int*)d_in[2];
    const int*   recover = (const int*)d_in[3];

    const long long NB = in_sizes[2];
    const long long L  = in_sizes[0] / NB;
    const long long D  = in_sizes[1] / in_sizes[0];
    const long long B  = (long long)out_size / (D + 1) - NB * L;
    const long long N  = NB / B;
    const long long MAX_LEN = N * L;

    float* out = (float*)d_out;
    float* src_out     = out;
    float* mb_out      = out + (size_t)MAX_LEN * B;
    float* hidden      = mb_out + (size_t)MAX_LEN * B * D;
    float* lengths_out = hidden + (size_t)B * D;

    {
        int n4 = (int)((B * D) / 4);
        zero_hidden_kernel<<<(n4 + 255) / 256, 256>>>(hidden, n4);
    }
    {
        fused_scatter_kernel<<<(unsigned)NB, 256>>>(src, mb, lengths, recover,
                                                    src_out, mb_out, hidden, lengths_out,
                                                    (int)B, (int)N, (int)D, (int)NB,
                                                    (int)MAX_LEN);
    }
}

// round 3
// speedup vs baseline: 1.1783x; 1.0340x over previous
#include <cuda_runtime.h>
#include <stdint.h>

// Ragged node-batch -> batch reconstruction.
// Inputs: src [L,NB], memory_bank [L,NB,D], lengths [NB], recover [NB]
// Output (flat): src_out [MAX_LEN,B], mb_out [MAX_LEN,B,D], hidden [B,D], lengths_out [B]
// B=32, N=64, L=128, D=256, NB=2048, MAX_LEN=8192 (derived from sizes).

__global__ void zero_hidden_kernel(float* __restrict__ hidden, int n4)
{
    int i = blockIdx.x * blockDim.x + threadIdx.x;
    if (i < n4)
        reinterpret_cast<float4*>(hidden)[i] = make_float4(0.f, 0.f, 0.f, 0.f);
}

// One block per node (b, n), 256 threads. lane = float4 column (64/row),
// rsub = row subgroup (4 rows in flight per block iteration).
__global__ void __launch_bounds__(256)
fused_scatter_kernel(const float* __restrict__ src,
                     const float* __restrict__ mb,
                     const int* __restrict__ lengths,
                     const int* __restrict__ recover,
                     float* __restrict__ src_out,
                     float* __restrict__ mb_out,
                     float* __restrict__ hidden,
                     float* __restrict__ lengths_out,
                     int B, int N, int D, int NB, int MAX_LEN)
{
    const int nb = blockIdx.x;
    const int b = nb / N;
    const int n = nb - b * N;
    const int tid  = threadIdx.x;
    const int lanes = D >> 2;              // 64 float4 lanes per row
    const int lane = tid & (lanes - 1);
    const int rsub = tid >> 6;             // 0..3

    __shared__ int s_len[64];
    __shared__ float4 s_acc[4][64];

    for (int i = tid; i < N; i += blockDim.x)
        s_len[i] = lengths[b * N + i];
    __syncthreads();

    int off = 0, len_b = 0;
    #pragma unroll 8
    for (int i = 0; i < N; ++i) {
        int li = s_len[i];
        len_b += li;
        if (i < n) off += li;
    }
    const int len = s_len[n];

    // ---------------- scatter valid rows: 4-deep unrolled, MLP=4 ------------
    const size_t in_stride  = (size_t)NB * lanes;   // float4 elems per token row
    const size_t out_stride = (size_t)B * lanes;
    const size_t is4 = in_stride * 4;               // thread's row step (p += 4)
    const size_t os4 = out_stride * 4;

    const float4* __restrict__ ip =
        reinterpret_cast<const float4*>(mb) + (size_t)nb * lanes + lane
        + (size_t)rsub * in_stride;
    float4* __restrict__ op =
        reinterpret_cast<float4*>(mb_out) + ((size_t)off * B + b) * lanes + lane
        + (size_t)rsub * out_stride;

    // number of rows this thread handles: p = rsub, rsub+4, ... < len
    int iters = (len > rsub) ? ((len - rsub + 3) >> 2) : 0;

    float4 acc = make_float4(0.f, 0.f, 0.f, 0.f);
    int it = 0;
    for (; it + 4 <= iters; it += 4) {
        float4 v0 = ip[0];
        float4 v1 = ip[is4];
        float4 v2 = ip[is4 * 2];
        float4 v3 = ip[is4 * 3];
        op[0]       = v0;
        op[os4]     = v1;
        op[os4 * 2] = v2;
        op[os4 * 3] = v3;
        acc.x += v0.x + v1.x + v2.x + v3.x;
        acc.y += v0.y + v1.y + v2.y + v3.y;
        acc.z += v0.z + v1.z + v2.z + v3.z;
        acc.w += v0.w + v1.w + v2.w + v3.w;
        ip += is4 * 4;
        op += os4 * 4;
    }
    for (; it < iters; ++it) {
        float4 v = ip[0];
        op[0] = v;
        acc.x += v.x; acc.y += v.y; acc.z += v.z; acc.w += v.w;
        ip += is4;
        op += os4;
    }
    s_acc[rsub][lane] = acc;

    // ---------------- src scatter: src_g[b,n,p] = src[p, recover[nb]] -------
    const int rc = recover[nb];
    for (int q = tid; q < len; q += blockDim.x)
        src_out[(size_t)(off + q) * B + b] = src[(size_t)q * NB + rc];

    // ---------------- tail fill (before sync: hides barrier skew) -----------
    {
        const float4 z4 = make_float4(0.f, 0.f, 0.f, 0.f);
        float4* tp = reinterpret_cast<float4*>(mb_out)
                   + ((size_t)(len_b + rsub * N + n) * B + b) * lanes + lane;
        const size_t tstep = (size_t)4 * N * B * lanes;
        for (int r = len_b + rsub * N + n; r < MAX_LEN; r += 4 * N) {
            *tp = z4;
            tp += tstep;
        }
    }
    {
        const int T = MAX_LEN - len_b;
        for (int i = n * blockDim.x + tid; i < T; i += N * blockDim.x)
            src_out[(size_t)(len_b + i) * B + b] = 1.0f;
    }

    __syncthreads();

    // ---------------- hidden partial: reduce 4 subgroups -> 4 atomics -------
    if (rsub == 0 && len_b > 0) {
        float4 a0 = s_acc[0][lane], a1 = s_acc[1][lane];
        float4 a2 = s_acc[2][lane], a3 = s_acc[3][lane];
        float inv = 1.0f / (float)len_b;
        float* h = hidden + (size_t)b * D + lane * 4;
        atomicAdd(h + 0, (a0.x + a1.x + a2.x + a3.x) * inv);
        atomicAdd(h + 1, (a0.y + a1.y + a2.y + a3.y) * inv);
        atomicAdd(h + 2, (a0.z + a1.z + a2.z + a3.z) * inv);
        atomicAdd(h + 3, (a0.w + a1.w + a2.w + a3.w) * inv);
    }

    if (n == 0 && tid == 0)
        lengths_out[b] = (float)len_b;
}

extern "C" void kernel_launch(void* const* d_in, const int* in_sizes, int n_in,
                              void* d_out, int out_size)
{
    const float* src     = (const float*)d_in[0];
    const float* mb      = (const float*)d_in[1];
    const int*   lengths = (const int*)d_in[2];
    const int*   recover = (const int*)d_in[3];

    const long long NB = in_sizes[2];
    const long long L  = in_sizes[0] / NB;
    const long long D  = in_sizes[1] / in_sizes[0];
    const long long B  = (long long)out_size / (D + 1) - NB * L;
    const long long N  = NB / B;
    const long long MAX_LEN = N * L;

    float* out = (float*)d_out;
    float* src_out     = out;
    float* mb_out      = out + (size_t)MAX_LEN * B;
    float* hidden      = mb_out + (size_t)MAX_LEN * B * D;
    float* lengths_out = hidden + (size_t)B * D;

    {
        int n4 = (int)((B * D) / 4);
        zero_hidden_kernel<<<(n4 + 255) / 256, 256>>>(hidden, n4);
    }
    fused_scatter_kernel<<<(unsigned)NB, 256>>>(src, mb, lengths, recover,
                                                src_out, mb_out, hidden, lengths_out,
                                                (int)B, (int)N, (int)D, (int)NB,
                                                (int)MAX_LEN);
}